// round 1
// baseline (speedup 1.0000x reference)
#include <cuda_runtime.h>
#include <math.h>

#define NG 4096
#define W_IMG 256
#define H_IMG 256
#define TSZ 64

// Per-gaussian attribute indices in scratch arrays
// 0 mx, 1 my, 2 c00, 3 c11, 4 csum, 5 op, 6 r, 7 g, 8 b, 9 z,
// 10 rminx, 11 rmaxx, 12 rminy, 13 rmaxy
#define NATTR 14

__device__ float g_zraw[NG];
__device__ float g_tmp[NATTR][NG];   // unsorted
__device__ float g_srt[NATTR][NG];   // sorted by z

// ---------------------------------------------------------------------------
// Kernel 1: per-gaussian projection / preprocessing
// ---------------------------------------------------------------------------
__global__ void prep_kernel(const float* __restrict__ xyz,
                            const float* __restrict__ cov_world,
                            const float* __restrict__ colors,
                            const float* __restrict__ opacity,
                            const float* __restrict__ w2c,
                            const float* __restrict__ focal,
                            const float* __restrict__ pp)
{
    int i = blockIdx.x * blockDim.x + threadIdx.x;
    if (i >= NG) return;

    float R00 = w2c[0],  R01 = w2c[1],  R02 = w2c[2],  t0 = w2c[3];
    float R10 = w2c[4],  R11 = w2c[5],  R12 = w2c[6],  t1 = w2c[7];
    float R20 = w2c[8],  R21 = w2c[9],  R22 = w2c[10], t2 = w2c[11];

    float p0 = xyz[i*3+0], p1 = xyz[i*3+1], p2 = xyz[i*3+2];
    float cam0 = R00*p0 + R01*p1 + R02*p2 + t0;
    float cam1 = R10*p0 + R11*p1 + R12*p2 + t1;
    float cam2 = R20*p0 + R21*p1 + R22*p2 + t2;

    float zr = cam2;
    float z  = fmaxf(zr, 1e-6f);
    float fx = focal[0], fy = focal[1];
    float mx = fx * cam0 / z + pp[0];
    float my = fy * cam1 / z + pp[1];

    // cov_cam = R * S * R^T
    float S[3][3];
    #pragma unroll
    for (int r = 0; r < 3; r++)
        #pragma unroll
        for (int c = 0; c < 3; c++)
            S[r][c] = cov_world[i*9 + r*3 + c];

    float Rm[3][3] = {{R00,R01,R02},{R10,R11,R12},{R20,R21,R22}};
    float M[3][3], C[3][3];
    #pragma unroll
    for (int r = 0; r < 3; r++)
        #pragma unroll
        for (int c = 0; c < 3; c++)
            M[r][c] = Rm[r][0]*S[0][c] + Rm[r][1]*S[1][c] + Rm[r][2]*S[2][c];
    #pragma unroll
    for (int r = 0; r < 3; r++)
        #pragma unroll
        for (int c = 0; c < 3; c++)
            C[r][c] = M[r][0]*Rm[c][0] + M[r][1]*Rm[c][1] + M[r][2]*Rm[c][2];

    // Jacobian rows
    float J00 = fx / z, J02 = -fx * cam0 / (z * z);
    float J11 = fy / z, J12 = -fy * cam1 / (z * z);
    // t0v = J0 * C  (J0 = [J00, 0, J02])
    float t0v0 = J00*C[0][0] + J02*C[2][0];
    float t0v1 = J00*C[0][1] + J02*C[2][1];
    float t0v2 = J00*C[0][2] + J02*C[2][2];
    // t1v = J1 * C  (J1 = [0, J11, J12])
    float t1v0 = J11*C[1][0] + J12*C[2][0];
    float t1v1 = J11*C[1][1] + J12*C[2][1];
    float t1v2 = J11*C[1][2] + J12*C[2][2];

    float a = t0v0*J00 + t0v2*J02 + 0.3f;          // v00 + 0.3
    float b = t0v1*J11 + t0v2*J12;                 // v01
    float c = t1v0*J00 + t1v2*J02;                 // v10
    float d = t1v1*J11 + t1v2*J12 + 0.3f;          // v11 + 0.3

    float disc   = sqrtf(fmaxf(0.25f*(a-d)*(a-d) + b*c, 0.0f));
    float maxeig = fmaxf(0.5f*(a+d) + disc, 1e-8f);
    float radius = fminf(3.0f * sqrtf(maxeig), 64.0f);
    float det    = a*d - b*c;
    float c00  = d / det;
    float c11  = a / det;
    float csum = (-b - c) / det;

    float opv = opacity[i];
    bool valid = (zr > 0.1f) && (opv > 1e-4f) && (radius > 0.25f);
    valid = valid && (mx + radius >= -1.0f) && (mx - radius < (float)W_IMG + 1.0f);
    valid = valid && (my + radius >= -1.0f) && (my - radius < (float)H_IMG + 1.0f);

    float radii = ceilf(radius);
    float rminx = fminf(fmaxf(floorf(mx - radii), 0.0f), (float)(W_IMG - 1));
    float rmaxx = fminf(fmaxf(ceilf (mx + radii), 0.0f), (float)(W_IMG - 1));
    float rminy = fminf(fmaxf(floorf(my - radii), 0.0f), (float)(H_IMG - 1));
    float rmaxy = fminf(fmaxf(ceilf (my + radii), 0.0f), (float)(H_IMG - 1));
    if (!valid) { rminx = 1e9f; rmaxx = -1e9f; rminy = 1e9f; rmaxy = -1e9f; }

    g_zraw[i]     = zr;
    g_tmp[0][i]   = mx;
    g_tmp[1][i]   = my;
    g_tmp[2][i]   = c00;
    g_tmp[3][i]   = c11;
    g_tmp[4][i]   = csum;
    g_tmp[5][i]   = opv;
    g_tmp[6][i]   = colors[i*3+0];
    g_tmp[7][i]   = colors[i*3+1];
    g_tmp[8][i]   = colors[i*3+2];
    g_tmp[9][i]   = zr;
    g_tmp[10][i]  = rminx;
    g_tmp[11][i]  = rmaxx;
    g_tmp[12][i]  = rminy;
    g_tmp[13][i]  = rmaxy;
}

// ---------------------------------------------------------------------------
// Kernel 2: stable rank-sort by z (O(N^2) compare against shared z) + scatter
// ---------------------------------------------------------------------------
__global__ void sort_scatter_kernel()
{
    __shared__ float zsh[NG];
    for (int j = threadIdx.x; j < NG; j += blockDim.x)
        zsh[j] = g_zraw[j];
    __syncthreads();

    int i = blockIdx.x * blockDim.x + threadIdx.x;
    if (i >= NG) return;
    float zi = zsh[i];
    int rank = 0;
    for (int j = 0; j < NG; j++) {
        float zj = zsh[j];
        rank += (zj < zi) || (zj == zi && j < i);
    }
    #pragma unroll
    for (int k = 0; k < NATTR; k++)
        g_srt[k][rank] = g_tmp[k][i];
}

// ---------------------------------------------------------------------------
// Kernel 3: tile rasterizer. One block = 16x16 pixels (1 px / thread),
// 16 blocks per 64x64 tile, 256 blocks total. Gaussians streamed through
// shared memory in chunks of 256 with order-preserving compaction against
// the tile-level overlap predicate (exact reference semantics).
// ---------------------------------------------------------------------------
__global__ void __launch_bounds__(256)
render_kernel(const float* __restrict__ bg, float* __restrict__ out)
{
    const int bx = blockIdx.x & 15;
    const int by = blockIdx.x >> 4;
    const int lx = threadIdx.x & 15;
    const int ly = threadIdx.x >> 4;
    const int px = bx * 16 + lx;
    const int py = by * 16 + ly;

    const float x0f = (float)((px >> 6) << 6);   // tile origin
    const float y0f = (float)((py >> 6) << 6);
    const float cx = (float)px + 0.5f;
    const float cy = (float)py + 0.5f;

    __shared__ float s_mx[256], s_my[256], s_c00[256], s_c11[256], s_cs[256];
    __shared__ float s_op[256], s_r[256], s_g[256], s_b[256], s_z[256];
    __shared__ int warp_cnt[8];

    float T = 1.0f;
    float accR = 0.f, accG = 0.f, accB = 0.f, acc = 0.f, dnum = 0.f;

    const int warp = threadIdx.x >> 5;
    const int lane = threadIdx.x & 31;

    for (int base = 0; base < NG; base += 256) {
        int gi = base + threadIdx.x;

        float rminx = g_srt[10][gi];
        float rmaxx = g_srt[11][gi];
        float rminy = g_srt[12][gi];
        float rmaxy = g_srt[13][gi];
        bool pred = (rmaxx >= x0f) && (rminx < x0f + (float)TSZ) &&
                    (rmaxy >= y0f) && (rminy < y0f + (float)TSZ);

        unsigned mask = __ballot_sync(0xffffffffu, pred);
        if (lane == 0) warp_cnt[warp] = __popc(mask);
        __syncthreads();

        int offset = 0, cnt = 0;
        #pragma unroll
        for (int w = 0; w < 8; w++) {
            int c = warp_cnt[w];
            if (w < warp) offset += c;
            cnt += c;
        }
        if (pred) {
            int pos = offset + __popc(mask & ((1u << lane) - 1u));
            s_mx [pos] = g_srt[0][gi];
            s_my [pos] = g_srt[1][gi];
            s_c00[pos] = g_srt[2][gi];
            s_c11[pos] = g_srt[3][gi];
            s_cs [pos] = g_srt[4][gi];
            s_op [pos] = g_srt[5][gi];
            s_r  [pos] = g_srt[6][gi];
            s_g  [pos] = g_srt[7][gi];
            s_b  [pos] = g_srt[8][gi];
            s_z  [pos] = g_srt[9][gi];
        }
        __syncthreads();

        for (int k = 0; k < cnt; k++) {
            float dx = cx - s_mx[k];
            float dy = cy - s_my[k];
            float maha = dx*dx*s_c00[k] + dy*dy*s_c11[k] + dx*dy*s_cs[k];
            if (maha <= 9.0f) {               // NaN -> false, matches jnp.where
                float alpha = fminf(expf(-0.5f * maha) * s_op[k], 0.99f);
                if (alpha >= (1.0f / 255.0f)) {
                    float w = T * alpha;
                    accR += w * s_r[k];
                    accG += w * s_g[k];
                    accB += w * s_b[k];
                    acc  += w;
                    dnum += w * s_z[k];
                    T *= (1.0f - alpha);
                }
            }
        }

        if (__syncthreads_and(T < 1e-7f)) break;   // also serves as loop barrier
    }

    float bgr = bg[0], bgg = bg[1], bgb = bg[2];
    float Rv = accR + (1.0f - acc) * bgr;
    float Gv = accG + (1.0f - acc) * bgg;
    float Bv = accB + (1.0f - acc) * bgb;
    Rv = fminf(fmaxf(Rv, 0.0f), 1.0f);
    Gv = fminf(fmaxf(Gv, 0.0f), 1.0f);
    Bv = fminf(fmaxf(Bv, 0.0f), 1.0f);
    float A = fminf(fmaxf(acc, 0.0f), 1.0f);
    float depth = (acc > 0.0f) ? (dnum / fmaxf(acc, 1e-8f)) : 0.0f;

    int o = (py * W_IMG + px) * 5;
    out[o+0] = Rv;
    out[o+1] = Gv;
    out[o+2] = Bv;
    out[o+3] = A;
    out[o+4] = depth;
}

// ---------------------------------------------------------------------------
extern "C" void kernel_launch(void* const* d_in, const int* in_sizes, int n_in,
                              void* d_out, int out_size)
{
    const float* xyz     = (const float*)d_in[0];
    const float* cov     = (const float*)d_in[1];
    const float* colors  = (const float*)d_in[2];
    const float* opacity = (const float*)d_in[3];
    const float* w2c     = (const float*)d_in[4];
    const float* focal   = (const float*)d_in[5];
    const float* pp      = (const float*)d_in[6];
    const float* bg      = (const float*)d_in[7];
    float* out = (float*)d_out;

    prep_kernel<<<NG / 256, 256>>>(xyz, cov, colors, opacity, w2c, focal, pp);
    sort_scatter_kernel<<<NG / 256, 256>>>();
    render_kernel<<<(W_IMG / 16) * (H_IMG / 16), 256>>>(bg, out);
}

// round 2
// speedup vs baseline: 1.0009x; 1.0009x over previous
#include <cuda_runtime.h>
#include <math.h>

#define NG 4096
#define W_IMG 256
#define H_IMG 256
#define TSZ 64

// Per-gaussian attribute indices in scratch arrays
// 0 mx, 1 my, 2 c00, 3 c11, 4 csum, 5 op, 6 r, 7 g, 8 b, 9 z,
// 10 rminx, 11 rmaxx, 12 rminy, 13 rmaxy
#define NATTR 14

__device__ float g_zraw[NG];
__device__ float g_tmp[NATTR][NG];   // unsorted
__device__ float g_srt[NATTR][NG];   // sorted by z

// ---------------------------------------------------------------------------
// Kernel 1: per-gaussian projection / preprocessing
// ---------------------------------------------------------------------------
__global__ void prep_kernel(const float* __restrict__ xyz,
                            const float* __restrict__ cov_world,
                            const float* __restrict__ colors,
                            const float* __restrict__ opacity,
                            const float* __restrict__ w2c,
                            const float* __restrict__ focal,
                            const float* __restrict__ pp)
{
    int i = blockIdx.x * blockDim.x + threadIdx.x;
    if (i >= NG) return;

    float R00 = w2c[0],  R01 = w2c[1],  R02 = w2c[2],  t0 = w2c[3];
    float R10 = w2c[4],  R11 = w2c[5],  R12 = w2c[6],  t1 = w2c[7];
    float R20 = w2c[8],  R21 = w2c[9],  R22 = w2c[10], t2 = w2c[11];

    float p0 = xyz[i*3+0], p1 = xyz[i*3+1], p2 = xyz[i*3+2];
    float cam0 = R00*p0 + R01*p1 + R02*p2 + t0;
    float cam1 = R10*p0 + R11*p1 + R12*p2 + t1;
    float cam2 = R20*p0 + R21*p1 + R22*p2 + t2;

    float zr = cam2;
    float z  = fmaxf(zr, 1e-6f);
    float fx = focal[0], fy = focal[1];
    float mx = fx * cam0 / z + pp[0];
    float my = fy * cam1 / z + pp[1];

    // cov_cam = R * S * R^T
    float S[3][3];
    #pragma unroll
    for (int r = 0; r < 3; r++)
        #pragma unroll
        for (int c = 0; c < 3; c++)
            S[r][c] = cov_world[i*9 + r*3 + c];

    float Rm[3][3] = {{R00,R01,R02},{R10,R11,R12},{R20,R21,R22}};
    float M[3][3], C[3][3];
    #pragma unroll
    for (int r = 0; r < 3; r++)
        #pragma unroll
        for (int c = 0; c < 3; c++)
            M[r][c] = Rm[r][0]*S[0][c] + Rm[r][1]*S[1][c] + Rm[r][2]*S[2][c];
    #pragma unroll
    for (int r = 0; r < 3; r++)
        #pragma unroll
        for (int c = 0; c < 3; c++)
            C[r][c] = M[r][0]*Rm[c][0] + M[r][1]*Rm[c][1] + M[r][2]*Rm[c][2];

    // Jacobian rows
    float J00 = fx / z, J02 = -fx * cam0 / (z * z);
    float J11 = fy / z, J12 = -fy * cam1 / (z * z);
    // t0v = J0 * C  (J0 = [J00, 0, J02])
    float t0v0 = J00*C[0][0] + J02*C[2][0];
    float t0v1 = J00*C[0][1] + J02*C[2][1];
    float t0v2 = J00*C[0][2] + J02*C[2][2];
    // t1v = J1 * C  (J1 = [0, J11, J12])
    float t1v0 = J11*C[1][0] + J12*C[2][0];
    float t1v1 = J11*C[1][1] + J12*C[2][1];
    float t1v2 = J11*C[1][2] + J12*C[2][2];

    float a = t0v0*J00 + t0v2*J02 + 0.3f;          // v00 + 0.3
    float b = t0v1*J11 + t0v2*J12;                 // v01
    float c = t1v0*J00 + t1v2*J02;                 // v10
    float d = t1v1*J11 + t1v2*J12 + 0.3f;          // v11 + 0.3

    float disc   = sqrtf(fmaxf(0.25f*(a-d)*(a-d) + b*c, 0.0f));
    float maxeig = fmaxf(0.5f*(a+d) + disc, 1e-8f);
    float radius = fminf(3.0f * sqrtf(maxeig), 64.0f);
    float det    = a*d - b*c;
    float c00  = d / det;
    float c11  = a / det;
    float csum = (-b - c) / det;

    float opv = opacity[i];
    bool valid = (zr > 0.1f) && (opv > 1e-4f) && (radius > 0.25f);
    valid = valid && (mx + radius >= -1.0f) && (mx - radius < (float)W_IMG + 1.0f);
    valid = valid && (my + radius >= -1.0f) && (my - radius < (float)H_IMG + 1.0f);

    float radii = ceilf(radius);
    float rminx = fminf(fmaxf(floorf(mx - radii), 0.0f), (float)(W_IMG - 1));
    float rmaxx = fminf(fmaxf(ceilf (mx + radii), 0.0f), (float)(W_IMG - 1));
    float rminy = fminf(fmaxf(floorf(my - radii), 0.0f), (float)(H_IMG - 1));
    float rmaxy = fminf(fmaxf(ceilf (my + radii), 0.0f), (float)(H_IMG - 1));
    if (!valid) { rminx = 1e9f; rmaxx = -1e9f; rminy = 1e9f; rmaxy = -1e9f; }

    g_zraw[i]     = zr;
    g_tmp[0][i]   = mx;
    g_tmp[1][i]   = my;
    g_tmp[2][i]   = c00;
    g_tmp[3][i]   = c11;
    g_tmp[4][i]   = csum;
    g_tmp[5][i]   = opv;
    g_tmp[6][i]   = colors[i*3+0];
    g_tmp[7][i]   = colors[i*3+1];
    g_tmp[8][i]   = colors[i*3+2];
    g_tmp[9][i]   = zr;
    g_tmp[10][i]  = rminx;
    g_tmp[11][i]  = rmaxx;
    g_tmp[12][i]  = rminy;
    g_tmp[13][i]  = rmaxy;
}

// ---------------------------------------------------------------------------
// Kernel 2: stable rank-sort by z (O(N^2) compare against shared z) + scatter
// ---------------------------------------------------------------------------
__global__ void sort_scatter_kernel()
{
    __shared__ float zsh[NG];
    for (int j = threadIdx.x; j < NG; j += blockDim.x)
        zsh[j] = g_zraw[j];
    __syncthreads();

    int i = blockIdx.x * blockDim.x + threadIdx.x;
    if (i >= NG) return;
    float zi = zsh[i];
    int rank = 0;
    for (int j = 0; j < NG; j++) {
        float zj = zsh[j];
        rank += (zj < zi) || (zj == zi && j < i);
    }
    #pragma unroll
    for (int k = 0; k < NATTR; k++)
        g_srt[k][rank] = g_tmp[k][i];
}

// ---------------------------------------------------------------------------
// Kernel 3: tile rasterizer. One block = 16x16 pixels (1 px / thread),
// 16 blocks per 64x64 tile, 256 blocks total. Gaussians streamed through
// shared memory in chunks of 256 with order-preserving compaction against
// the tile-level overlap predicate (exact reference semantics).
// ---------------------------------------------------------------------------
__global__ void __launch_bounds__(256)
render_kernel(const float* __restrict__ bg, float* __restrict__ out)
{
    const int bx = blockIdx.x & 15;
    const int by = blockIdx.x >> 4;
    const int lx = threadIdx.x & 15;
    const int ly = threadIdx.x >> 4;
    const int px = bx * 16 + lx;
    const int py = by * 16 + ly;

    const float x0f = (float)((px >> 6) << 6);   // tile origin
    const float y0f = (float)((py >> 6) << 6);
    const float cx = (float)px + 0.5f;
    const float cy = (float)py + 0.5f;

    __shared__ float s_mx[256], s_my[256], s_c00[256], s_c11[256], s_cs[256];
    __shared__ float s_op[256], s_r[256], s_g[256], s_b[256], s_z[256];
    __shared__ int warp_cnt[8];

    float T = 1.0f;
    float accR = 0.f, accG = 0.f, accB = 0.f, acc = 0.f, dnum = 0.f;

    const int warp = threadIdx.x >> 5;
    const int lane = threadIdx.x & 31;

    for (int base = 0; base < NG; base += 256) {
        int gi = base + threadIdx.x;

        float rminx = g_srt[10][gi];
        float rmaxx = g_srt[11][gi];
        float rminy = g_srt[12][gi];
        float rmaxy = g_srt[13][gi];
        bool pred = (rmaxx >= x0f) && (rminx < x0f + (float)TSZ) &&
                    (rmaxy >= y0f) && (rminy < y0f + (float)TSZ);

        unsigned mask = __ballot_sync(0xffffffffu, pred);
        if (lane == 0) warp_cnt[warp] = __popc(mask);
        __syncthreads();

        int offset = 0, cnt = 0;
        #pragma unroll
        for (int w = 0; w < 8; w++) {
            int c = warp_cnt[w];
            if (w < warp) offset += c;
            cnt += c;
        }
        if (pred) {
            int pos = offset + __popc(mask & ((1u << lane) - 1u));
            s_mx [pos] = g_srt[0][gi];
            s_my [pos] = g_srt[1][gi];
            s_c00[pos] = g_srt[2][gi];
            s_c11[pos] = g_srt[3][gi];
            s_cs [pos] = g_srt[4][gi];
            s_op [pos] = g_srt[5][gi];
            s_r  [pos] = g_srt[6][gi];
            s_g  [pos] = g_srt[7][gi];
            s_b  [pos] = g_srt[8][gi];
            s_z  [pos] = g_srt[9][gi];
        }
        __syncthreads();

        for (int k = 0; k < cnt; k++) {
            float dx = cx - s_mx[k];
            float dy = cy - s_my[k];
            float maha = dx*dx*s_c00[k] + dy*dy*s_c11[k] + dx*dy*s_cs[k];
            if (maha <= 9.0f) {               // NaN -> false, matches jnp.where
                float alpha = fminf(expf(-0.5f * maha) * s_op[k], 0.99f);
                if (alpha >= (1.0f / 255.0f)) {
                    float w = T * alpha;
                    accR += w * s_r[k];
                    accG += w * s_g[k];
                    accB += w * s_b[k];
                    acc  += w;
                    dnum += w * s_z[k];
                    T *= (1.0f - alpha);
                }
            }
        }

        if (__syncthreads_and(T < 1e-7f)) break;   // also serves as loop barrier
    }

    float bgr = bg[0], bgg = bg[1], bgb = bg[2];
    float Rv = accR + (1.0f - acc) * bgr;
    float Gv = accG + (1.0f - acc) * bgg;
    float Bv = accB + (1.0f - acc) * bgb;
    Rv = fminf(fmaxf(Rv, 0.0f), 1.0f);
    Gv = fminf(fmaxf(Gv, 0.0f), 1.0f);
    Bv = fminf(fmaxf(Bv, 0.0f), 1.0f);
    float A = fminf(fmaxf(acc, 0.0f), 1.0f);
    float depth = (acc > 0.0f) ? (dnum / fmaxf(acc, 1e-8f)) : 0.0f;

    int o = (py * W_IMG + px) * 5;
    out[o+0] = Rv;
    out[o+1] = Gv;
    out[o+2] = Bv;
    out[o+3] = A;
    out[o+4] = depth;
}

// ---------------------------------------------------------------------------
extern "C" void kernel_launch(void* const* d_in, const int* in_sizes, int n_in,
                              void* d_out, int out_size)
{
    const float* xyz     = (const float*)d_in[0];
    const float* cov     = (const float*)d_in[1];
    const float* colors  = (const float*)d_in[2];
    const float* opacity = (const float*)d_in[3];
    const float* w2c     = (const float*)d_in[4];
    const float* focal   = (const float*)d_in[5];
    const float* pp      = (const float*)d_in[6];
    const float* bg      = (const float*)d_in[7];
    float* out = (float*)d_out;

    prep_kernel<<<NG / 256, 256>>>(xyz, cov, colors, opacity, w2c, focal, pp);
    sort_scatter_kernel<<<NG / 256, 256>>>();
    render_kernel<<<(W_IMG / 16) * (H_IMG / 16), 256>>>(bg, out);
}